// round 11
// baseline (speedup 1.0000x reference)
#include <cuda_runtime.h>
#include <cuda_bf16.h>
#include <cstdint>
#include <math.h>

#define BDIM 8192
#define MDIM 256
#define GBM 128
#define GBN 128
#define NPANEL (BDIM / GBM)      // 64
#define NJT    (BDIM / GBN)      // 64
#define NJOBS  (NPANEL * NJT)    // 4096
#define NCTA   148

#define A_STRIDE 264
#define A_STRIDE_B (A_STRIDE * 2)        // 528
#define TILE_BYTES (GBM * A_STRIDE_B)    // 67584

// ---- device scratch ----
__device__ __align__(16) __nv_bfloat16 g_hzb[BDIM * MDIM];
__device__ __align__(16) __nv_bfloat16 g_hyb[BDIM * MDIM];
__device__ float g_Ssuf[MDIM * MDIM];
__device__ float g_diag[BDIM];
__device__ float g_psum[BDIM];
__device__ int   g_done[NPANEL];
__device__ int   g_barA, g_relA, g_barB, g_relB, g_fin;

// ============================ PTX helpers ============================
__device__ __forceinline__ uint32_t smem_u32(const void* p) {
    uint32_t a;
    asm("{ .reg .u64 t; cvta.to.shared.u64 t, %1; cvt.u32.u64 %0, t; }" : "=r"(a) : "l"(p));
    return a;
}
__device__ __forceinline__ void ldmatrix_x4(uint32_t* r, uint32_t addr) {
    asm volatile("ldmatrix.sync.aligned.m8n8.x4.shared.b16 {%0,%1,%2,%3}, [%4];"
                 : "=r"(r[0]), "=r"(r[1]), "=r"(r[2]), "=r"(r[3]) : "r"(addr));
}
__device__ __forceinline__ void mma_16816(float* c, const uint32_t* a,
                                          uint32_t b0, uint32_t b1) {
    asm volatile(
        "mma.sync.aligned.m16n8k16.row.col.f32.bf16.bf16.f32 "
        "{%0,%1,%2,%3}, {%4,%5,%6,%7}, {%8,%9}, {%0,%1,%2,%3};"
        : "+f"(c[0]), "+f"(c[1]), "+f"(c[2]), "+f"(c[3])
        : "r"(a[0]), "r"(a[1]), "r"(a[2]), "r"(a[3]), "r"(b0), "r"(b1));
}
__device__ __forceinline__ float ex2f(float x) {
    float y;
    asm("ex2.approx.ftz.f32 %0, %1;" : "=f"(y) : "f"(x));
    return y;
}
#define CP_ASYNC16(s, g) \
    asm volatile("cp.async.cg.shared.global [%0], [%1], 16;" :: "r"(s), "l"(g))
#define CP_COMMIT()  asm volatile("cp.async.commit_group;" ::: "memory")
#define CP_WAIT0()   asm volatile("cp.async.wait_group 0;" ::: "memory")

__device__ __forceinline__ void cp_tile(const __nv_bfloat16* __restrict__ g,
                                        uint32_t s, int tid) {
    int chunk = tid & 31;
    int row   = tid >> 5;
    const char* gp = (const char*)g + (size_t)row * 512 + chunk * 16;
    uint32_t sp = s + row * A_STRIDE_B + chunk * 16;
    #pragma unroll
    for (int r = 0; r < 16; r++) {
        CP_ASYNC16(sp, gp);
        gp += 8 * 512;
        sp += 8 * A_STRIDE_B;
    }
}

// grid-wide spin barrier (all NCTA CTAs resident: 1 CTA/SM by smem).
// The releaser of this barrier optionally resets the PREVIOUS barrier's state
// (everyone arriving here has passed it), keeping counters zero across graph replays.
__device__ __forceinline__ void grid_barrier(int* bar, int* rel,
                                             int* barPrev, int* relPrev) {
    __syncthreads();
    if (threadIdx.x == 0) {
        __threadfence();
        int a = atomicAdd(bar, 1);
        if (a == NCTA - 1) {
            if (barPrev) { *barPrev = 0; *((volatile int*)relPrev) = 0; }
            __threadfence();
            *((volatile int*)rel) = 1;
        }
        while (*((volatile int*)rel) == 0) { }
        __threadfence();
    }
    __syncthreads();
}

// ---------------------------------------------------------------------------
// GEMM tile step: mma for local tile k into accC, epilogue of accP interleaved
// ---------------------------------------------------------------------------
template <bool EPI>
__device__ __forceinline__ void tile_step(
    float (&accC)[4][4][4], float (&accP)[4][4][4], float (&rowsum)[8],
    int k, int jt0, int segn, uint32_t sA, uint32_t sB0, uint32_t sB1,
    uint32_t a_off, uint32_t b_off, int tid, float L2E, float ebias)
{
    #pragma unroll
    for (int mi = 0; mi < 4; mi++)
        #pragma unroll
        for (int nj = 0; nj < 4; nj++)
            #pragma unroll
            for (int c = 0; c < 4; c++) accC[mi][nj][c] = 0.f;

    if (k + 1 < segn) {
        cp_tile(g_hyb + (size_t)(jt0 + k + 1) * GBN * MDIM,
                ((k + 1) & 1) ? sB1 : sB0, tid);
        CP_COMMIT();
    }
    uint32_t sBcur = (k & 1) ? sB1 : sB0;

    #pragma unroll
    for (int ks = 0; ks < 16; ks++) {
        uint32_t af[4][4], bf[2][4];
        #pragma unroll
        for (int mi = 0; mi < 4; mi++)
            ldmatrix_x4(af[mi], sA + a_off + mi * 16 * A_STRIDE_B + ks * 32);
        #pragma unroll
        for (int nb = 0; nb < 2; nb++)
            ldmatrix_x4(bf[nb], sBcur + b_off + nb * 16 * A_STRIDE_B + ks * 32);
        #pragma unroll
        for (int mi = 0; mi < 4; mi++)
            #pragma unroll
            for (int nj = 0; nj < 4; nj++)
                mma_16816(accC[mi][nj], af[mi],
                          bf[nj >> 1][(nj & 1) * 2], bf[nj >> 1][(nj & 1) * 2 + 1]);
        if (EPI) {
            #pragma unroll
            for (int q = 0; q < 4; q++) {
                int v = ks * 4 + q;
                int mi = v >> 4, nj = (v >> 2) & 3, c = v & 3;
                rowsum[mi * 2 + (c >> 1)] += ex2f(fmaf(accP[mi][nj][c], L2E, ebias));
            }
        }
    }
    CP_WAIT0();
    __syncthreads();
}

// ---------------------------------------------------------------------------
// ONE persistent kernel: suffix -> barrier -> prep -> barrier -> scheduled GEMM
// grid = 148, block = 256
// ---------------------------------------------------------------------------
__global__ __launch_bounds__(256, 1)
void fused_kernel(const float* __restrict__ z,
                  const float* __restrict__ t,
                  const float* __restrict__ e,
                  const float* __restrict__ log_tau,
                  const float* __restrict__ E,
                  const float* __restrict__ L,
                  float* __restrict__ out) {
    extern __shared__ char smem[];
    __shared__ float sL[MDIM];
    __shared__ int s_last;
    uint32_t sA  = smem_u32(smem);
    uint32_t sB0 = sA + TILE_BYTES;
    uint32_t sB1 = sB0 + TILE_BYTES;

    int tid  = threadIdx.x;
    int cta  = blockIdx.x;
    int lane = tid & 31;
    int warp = tid >> 5;

    // ---------------- Phase 0: suffix sums of E + zero psum/done ----------------
    {
        int g = cta * 256 + tid;
        if (g < BDIM) g_psum[g] = 0.f;
        if (g < NPANEL) g_done[g] = 0;
        float* srow = (float*)smem;
        for (int k = cta; k < MDIM; k += NCTA) {
            srow[tid] = E[k * MDIM + tid];
            __syncthreads();
            float s = 0.f;
            for (int jj = MDIM - 1; jj >= tid; --jj) s += srow[jj];
            g_Ssuf[tid * MDIM + k] = s;
            __syncthreads();
        }
    }
    grid_barrier(&g_barA, &g_relA, 0, 0);

    // ---------------- Phase 1: prep (one warp per row) ----------------
    sL[tid] = L[tid];
    __syncthreads();
    {
        float inv_tau2 = __expf(-log_tau[0]);
        for (int i = cta * 8 + warp; i < BDIM; i += NCTA * 8) {
            float ti = t[i], ei = e[i];
            int lo = 0, hi = MDIM;
            while (lo < hi) { int mid = (lo + hi) >> 1; if (sL[mid] < ti) lo = mid + 1; else hi = mid; }
            int idx = lo;
            if (idx == 0) idx = 1;
            if (idx == MDIM) idx = MDIM - 1;

            float Llo = sL[idx - 1], Lhi = sL[idx];
            float slope_t = (ti - Llo) / (Lhi - Llo);
            float rden = 1.f / (float)(MDIM - idx);

            const float4* Elo4 = (const float4*)(E + (size_t)(idx - 1) * MDIM) + lane * 2;
            const float4* Ehi4 = (const float4*)(E + (size_t)idx * MDIM)       + lane * 2;
            const float4* Ss4  = (const float4*)(g_Ssuf + (size_t)idx * MDIM)  + lane * 2;
            const float4* z4   = (const float4*)(z + (size_t)i * MDIM)         + lane * 2;

            float yv[8], zv[8];
            float sy = 0.f, sz = 0.f, szy = 0.f;
            #pragma unroll
            for (int h = 0; h < 2; h++) {
                float4 el = Elo4[h], eh = Ehi4[h], ss = Ss4[h], zz = z4[h];
                float elc[4] = {el.x, el.y, el.z, el.w};
                float ehc[4] = {eh.x, eh.y, eh.z, eh.w};
                float ssc[4] = {ss.x, ss.y, ss.z, ss.w};
                float zzc[4] = {zz.x, zz.y, zz.z, zz.w};
                #pragma unroll
                for (int c = 0; c < 4; c++) {
                    float ylin = elc[c] + (ehc[c] - elc[c]) * slope_t;
                    float ycen = ssc[c] * rden;
                    float y = ylin * ei + ycen * (1.f - ei);
                    yv[h * 4 + c] = y;
                    zv[h * 4 + c] = zzc[c];
                    sy  = fmaf(y, y, sy);
                    sz  = fmaf(zzc[c], zzc[c], sz);
                    szy = fmaf(zzc[c], y, szy);
                }
            }
            #pragma unroll
            for (int o = 16; o; o >>= 1) {
                sy  += __shfl_xor_sync(0xffffffffu, sy,  o);
                sz  += __shfl_xor_sync(0xffffffffu, sz,  o);
                szy += __shfl_xor_sync(0xffffffffu, szy, o);
            }
            float ny = fmaxf(sqrtf(sy), 1e-12f);
            float nz = fmaxf(sqrtf(sz), 1e-12f);
            float scz = inv_tau2 / nz;
            float scy = 1.f / ny;

            uint4 hzp, hyp;
            __nv_bfloat162* hz2 = (__nv_bfloat162*)&hzp;
            __nv_bfloat162* hy2 = (__nv_bfloat162*)&hyp;
            #pragma unroll
            for (int p = 0; p < 4; p++) {
                hz2[p] = __floats2bfloat162_rn(zv[2*p] * scz, zv[2*p+1] * scz);
                hy2[p] = __floats2bfloat162_rn(yv[2*p] * scy, yv[2*p+1] * scy);
            }
            *(uint4*)(g_hzb + (size_t)i * MDIM + lane * 8) = hzp;
            *(uint4*)(g_hyb + (size_t)i * MDIM + lane * 8) = hyp;
            if (lane == 0) g_diag[i] = szy / (ny * nz);
        }
    }
    grid_barrier(&g_barB, &g_relB, &g_barA, &g_relA);

    // ---------------- Phase 2: scheduled GEMM + exp-sum + finalize ----------------
    int warp_m = warp >> 2;
    int warp_n = warp & 3;
    float Mconst = __expf(-log_tau[0]);
    const float L2E = 1.4426950408889634f;
    float ebias = -Mconst * L2E;

    uint32_t a_off = (uint32_t)((warp_m * 64 + (lane & 15)) * A_STRIDE_B + (lane >> 4) * 16);
    uint32_t b_off = (uint32_t)((warp_n * 32 + (lane & 7) + ((lane >> 4) << 3)) * A_STRIDE_B
                                + ((lane >> 3) & 1) * 16);

    int job = (cta * NJOBS) / NCTA;
    int jend = ((cta + 1) * NJOBS) / NCTA;

    float acc0[4][4][4], acc1[4][4][4];

    while (job < jend) {
        int panel = job >> 6;
        int jt0   = job & 63;
        int segn  = min(jend - job, 64 - jt0);
        int row0  = panel * GBM;

        cp_tile(g_hzb + (size_t)row0 * MDIM, sA, tid);
        cp_tile(g_hyb + (size_t)jt0 * GBN * MDIM, sB0, tid);
        CP_COMMIT();

        float rowsum[8];
        #pragma unroll
        for (int i = 0; i < 8; i++) rowsum[i] = 0.f;

        CP_WAIT0();
        __syncthreads();

        tile_step<false>(acc0, acc1, rowsum, 0, jt0, segn, sA, sB0, sB1,
                         a_off, b_off, tid, L2E, ebias);
        #pragma unroll 1
        for (int k = 1; k < segn; k++) {
            if (k & 1)
                tile_step<true>(acc1, acc0, rowsum, k, jt0, segn, sA, sB0, sB1,
                                a_off, b_off, tid, L2E, ebias);
            else
                tile_step<true>(acc0, acc1, rowsum, k, jt0, segn, sA, sB0, sB1,
                                a_off, b_off, tid, L2E, ebias);
        }
        // drain last tile's epilogue
        if ((segn - 1) & 1) {
            #pragma unroll
            for (int v = 0; v < 64; v++) {
                int mi = v >> 4, nj = (v >> 2) & 3, c = v & 3;
                rowsum[mi * 2 + (c >> 1)] += ex2f(fmaf(acc1[mi][nj][c], L2E, ebias));
            }
        } else {
            #pragma unroll
            for (int v = 0; v < 64; v++) {
                int mi = v >> 4, nj = (v >> 2) & 3, c = v & 3;
                rowsum[mi * 2 + (c >> 1)] += ex2f(fmaf(acc0[mi][nj][c], L2E, ebias));
            }
        }

        // reduce: lanes sharing a row differ in bits 0-1
        #pragma unroll
        for (int i = 0; i < 8; i++) {
            rowsum[i] += __shfl_xor_sync(0xffffffffu, rowsum[i], 1);
            rowsum[i] += __shfl_xor_sync(0xffffffffu, rowsum[i], 2);
        }
        float* red = (float*)smem;   // reuse A area (synced above)
        if ((lane & 3) == 0) {
            int g = lane >> 2;
            #pragma unroll
            for (int i = 0; i < 8; i++) {
                int row = warp_m * 64 + (i >> 1) * 16 + g + (i & 1) * 8;
                red[row * 4 + warp_n] = rowsum[i];
            }
        }
        __syncthreads();
        if (tid < GBM) {
            float s = red[tid * 4] + red[tid * 4 + 1] + red[tid * 4 + 2] + red[tid * 4 + 3];
            atomicAdd(&g_psum[row0 + tid], s);
        }
        __threadfence();
        __syncthreads();   // red reads done before next segment's A overwrite
        if (tid == 0)
            s_last = (atomicAdd(&g_done[panel], segn) + segn == NJT);
        __syncthreads();

        if (s_last) {
            __threadfence();
            if (tid < GBM) {
                int row = row0 + tid;
                float S = g_psum[row];
                float o = Mconst + logf(S) - g_diag[row] * Mconst - logf((float)BDIM);
                out[row] = fminf(fmaxf(o, -5.f), 15.f);
            }
            if (tid == 0) {
                g_done[panel] = 0;
                int f = atomicAdd(&g_fin, 1);
                if (f == NPANEL - 1) {   // last panel done: reset barrier B state
                    g_fin = 0;
                    g_barB = 0;
                    *((volatile int*)&g_relB) = 0;
                    __threadfence();
                }
            }
        }
        job += segn;
    }
}

// ---------------------------------------------------------------------------
extern "C" void kernel_launch(void* const* d_in, const int* in_sizes, int n_in,
                              void* d_out, int out_size) {
    const float* z       = (const float*)d_in[0];
    const float* t       = (const float*)d_in[1];
    const float* e       = (const float*)d_in[2];
    const float* log_tau = (const float*)d_in[3];
    const float* E       = (const float*)d_in[4];
    const float* L       = (const float*)d_in[5];
    float* out = (float*)d_out;

    const int smem_sz = 3 * TILE_BYTES;   // 202,752 B
    cudaFuncSetAttribute(fused_kernel, cudaFuncAttributeMaxDynamicSharedMemorySize, smem_sz);
    fused_kernel<<<NCTA, 256, smem_sz>>>(z, t, e, log_tau, E, L, out);
}

// round 12
// speedup vs baseline: 1.5481x; 1.5481x over previous
#include <cuda_runtime.h>
#include <cuda_bf16.h>
#include <cstdint>
#include <math.h>

#define BDIM 8192
#define MDIM 256
#define NSLICE 2
#define JSPAN (BDIM / NSLICE)   // 4096
#define GBM 128
#define GBN 128
#define TILES (JSPAN / GBN)     // 32
#define NPANEL (BDIM / GBM)     // 64

#define A_STRIDE 264                     // bf16 elems per smem row (256 + 8 pad)
#define A_STRIDE_B (A_STRIDE * 2)        // 528 bytes
#define TILE_BYTES (GBM * A_STRIDE_B)    // 67584

// ---- device scratch (no allocations allowed) ----
__device__ __align__(16) __nv_bfloat16 g_hzb[BDIM * MDIM];  // bf16(hz * inv_tau2)
__device__ __align__(16) __nv_bfloat16 g_hyb[BDIM * MDIM];  // bf16(hy)
__device__ float g_Ssuf[MDIM * MDIM];
__device__ float g_diag[BDIM];
__device__ float g_psum[NSLICE * BDIM];
__device__ int   g_done[NPANEL];

// ============================ PTX helpers ============================
__device__ __forceinline__ uint32_t smem_u32(const void* p) {
    uint32_t a;
    asm("{ .reg .u64 t; cvta.to.shared.u64 t, %1; cvt.u32.u64 %0, t; }" : "=r"(a) : "l"(p));
    return a;
}
__device__ __forceinline__ void ldmatrix_x4(uint32_t* r, uint32_t addr) {
    asm volatile("ldmatrix.sync.aligned.m8n8.x4.shared.b16 {%0,%1,%2,%3}, [%4];"
                 : "=r"(r[0]), "=r"(r[1]), "=r"(r[2]), "=r"(r[3]) : "r"(addr));
}
__device__ __forceinline__ void mma_16816(float* c, const uint32_t* a,
                                          uint32_t b0, uint32_t b1) {
    asm volatile(
        "mma.sync.aligned.m16n8k16.row.col.f32.bf16.bf16.f32 "
        "{%0,%1,%2,%3}, {%4,%5,%6,%7}, {%8,%9}, {%0,%1,%2,%3};"
        : "+f"(c[0]), "+f"(c[1]), "+f"(c[2]), "+f"(c[3])
        : "r"(a[0]), "r"(a[1]), "r"(a[2]), "r"(a[3]), "r"(b0), "r"(b1));
}
__device__ __forceinline__ float ex2f(float x) {
    float y;
    asm("ex2.approx.ftz.f32 %0, %1;" : "=f"(y) : "f"(x));
    return y;
}
#define CP_ASYNC16(s, g) \
    asm volatile("cp.async.cg.shared.global [%0], [%1], 16;" :: "r"(s), "l"(g))
#define CP_COMMIT()  asm volatile("cp.async.commit_group;" ::: "memory")
#define CP_WAIT0()   asm volatile("cp.async.wait_group 0;" ::: "memory")

// copy 128 rows x 512B into padded smem (stride 528B), 512 threads
__device__ __forceinline__ void cp_tile(const __nv_bfloat16* __restrict__ g,
                                        uint32_t s, int tid) {
    int chunk = tid & 31;
    int row   = tid >> 5;          // 0..15
    const char* gp = (const char*)g + (size_t)row * 512 + chunk * 16;
    uint32_t sp = s + row * A_STRIDE_B + chunk * 16;
    #pragma unroll
    for (int r = 0; r < 8; r++) {
        CP_ASYNC16(sp, gp);
        gp += 16 * 512;
        sp += 16 * A_STRIDE_B;
    }
}

// ---------------------------------------------------------------------------
// Kernel 1: suffix sums of E rows (censor term) + zero completion counters
// ---------------------------------------------------------------------------
__global__ void suffix_kernel(const float* __restrict__ E) {
    __shared__ float row[MDIM];
    int k = blockIdx.x, j = threadIdx.x;
    if (k == 0 && j < NPANEL) g_done[j] = 0;
    row[j] = E[k * MDIM + j];
    __syncthreads();
    float s = 0.f;
    for (int jj = MDIM - 1; jj >= j; --jj) s += row[jj];
    g_Ssuf[j * MDIM + k] = s;
}

// ---------------------------------------------------------------------------
// Kernel 2: prep — one warp per row (512-thread blocks, 16 warps)
// ---------------------------------------------------------------------------
__global__ __launch_bounds__(512)
void prep_kernel(const float* __restrict__ z,
                 const float* __restrict__ t,
                 const float* __restrict__ e,
                 const float* __restrict__ log_tau,
                 const float* __restrict__ E,
                 const float* __restrict__ L) {
    __shared__ float sL[MDIM];
    int tid = threadIdx.x;
    if (tid < MDIM) sL[tid] = L[tid];
    __syncthreads();

    int lane = tid & 31, warp = tid >> 5;
    int i = blockIdx.x * 16 + warp;

    float ti = t[i], ei = e[i];
    int lo = 0, hi = MDIM;
    while (lo < hi) { int mid = (lo + hi) >> 1; if (sL[mid] < ti) lo = mid + 1; else hi = mid; }
    int idx = lo;
    if (idx == 0) idx = 1;
    if (idx == MDIM) idx = MDIM - 1;

    float Llo = sL[idx - 1], Lhi = sL[idx];
    float slope_t = (ti - Llo) / (Lhi - Llo);
    float rden = 1.f / (float)(MDIM - idx);

    const float4* Elo4 = (const float4*)(E + (size_t)(idx - 1) * MDIM) + lane * 2;
    const float4* Ehi4 = (const float4*)(E + (size_t)idx * MDIM)       + lane * 2;
    const float4* Ss4  = (const float4*)(g_Ssuf + (size_t)idx * MDIM)  + lane * 2;
    const float4* z4   = (const float4*)(z + (size_t)i * MDIM)         + lane * 2;

    float yv[8], zv[8];
    float sy = 0.f, sz = 0.f, szy = 0.f;
    #pragma unroll
    for (int h = 0; h < 2; h++) {
        float4 el = Elo4[h], eh = Ehi4[h], ss = Ss4[h], zz = z4[h];
        float elc[4] = {el.x, el.y, el.z, el.w};
        float ehc[4] = {eh.x, eh.y, eh.z, eh.w};
        float ssc[4] = {ss.x, ss.y, ss.z, ss.w};
        float zzc[4] = {zz.x, zz.y, zz.z, zz.w};
        #pragma unroll
        for (int c = 0; c < 4; c++) {
            float ylin = elc[c] + (ehc[c] - elc[c]) * slope_t;
            float ycen = ssc[c] * rden;
            float y = ylin * ei + ycen * (1.f - ei);
            yv[h * 4 + c] = y;
            zv[h * 4 + c] = zzc[c];
            sy  = fmaf(y, y, sy);
            sz  = fmaf(zzc[c], zzc[c], sz);
            szy = fmaf(zzc[c], y, szy);
        }
    }
    #pragma unroll
    for (int o = 16; o; o >>= 1) {
        sy  += __shfl_xor_sync(0xffffffffu, sy,  o);
        sz  += __shfl_xor_sync(0xffffffffu, sz,  o);
        szy += __shfl_xor_sync(0xffffffffu, szy, o);
    }
    float ny = fmaxf(sqrtf(sy), 1e-12f);
    float nz = fmaxf(sqrtf(sz), 1e-12f);
    float inv_tau2 = __expf(-log_tau[0]);
    float scz = inv_tau2 / nz;
    float scy = 1.f / ny;

    uint4 hzp, hyp;
    __nv_bfloat162* hz2 = (__nv_bfloat162*)&hzp;
    __nv_bfloat162* hy2 = (__nv_bfloat162*)&hyp;
    #pragma unroll
    for (int p = 0; p < 4; p++) {
        hz2[p] = __floats2bfloat162_rn(zv[2*p] * scz, zv[2*p+1] * scz);
        hy2[p] = __floats2bfloat162_rn(yv[2*p] * scy, yv[2*p+1] * scy);
    }
    *(uint4*)(g_hzb + (size_t)i * MDIM + lane * 8) = hzp;
    *(uint4*)(g_hyb + (size_t)i * MDIM + lane * 8) = hyp;
    if (lane == 0) g_diag[i] = szy / (ny * nz);
}

// ---------------------------------------------------------------------------
// GEMM tile step (16 warps, warp tile 32x32):
// mma for tile n into accC, epilogue of accP (32 exps) interleaved 2/ks
// ---------------------------------------------------------------------------
template <bool EPI>
__device__ __forceinline__ void tile_step(
    float (&accC)[2][4][4], float (&accP)[2][4][4], float (&rowsum)[4],
    int n, uint32_t sA, uint32_t sB0, uint32_t sB1,
    uint32_t a_off, uint32_t b_off, int colbase, int tid,
    float L2E, float ebias)
{
    #pragma unroll
    for (int mi = 0; mi < 2; mi++)
        #pragma unroll
        for (int nj = 0; nj < 4; nj++)
            #pragma unroll
            for (int c = 0; c < 4; c++) accC[mi][nj][c] = 0.f;

    if (n + 1 < TILES) {
        cp_tile(g_hyb + (size_t)(colbase + (n + 1) * GBN) * MDIM,
                ((n + 1) & 1) ? sB1 : sB0, tid);
        CP_COMMIT();
    }
    uint32_t sBcur = (n & 1) ? sB1 : sB0;

    #pragma unroll
    for (int ks = 0; ks < 16; ks++) {
        uint32_t af[2][4], bf[2][4];
        #pragma unroll
        for (int mi = 0; mi < 2; mi++)
            ldmatrix_x4(af[mi], sA + a_off + mi * 16 * A_STRIDE_B + ks * 32);
        #pragma unroll
        for (int nb = 0; nb < 2; nb++)
            ldmatrix_x4(bf[nb], sBcur + b_off + nb * 16 * A_STRIDE_B + ks * 32);
        #pragma unroll
        for (int mi = 0; mi < 2; mi++)
            #pragma unroll
            for (int nj = 0; nj < 4; nj++)
                mma_16816(accC[mi][nj], af[mi],
                          bf[nj >> 1][(nj & 1) * 2], bf[nj >> 1][(nj & 1) * 2 + 1]);
        if (EPI) {
            #pragma unroll
            for (int q = 0; q < 2; q++) {
                int v = ks * 2 + q;                       // 0..31
                int mi = v >> 4, nj = (v >> 2) & 3, c = v & 3;
                rowsum[mi * 2 + (c >> 1)] += ex2f(fmaf(accP[mi][nj][c], L2E, ebias));
            }
        }
    }
    CP_WAIT0();
    __syncthreads();
}

// ---------------------------------------------------------------------------
// Kernel 3: bf16 mma.sync GEMM + pipelined exp-sum epilogue + merged finalize
// grid = (NSLICE, 64), block = 512 (16 warps: 4 M x 4 N, warp tile 32x32)
// ---------------------------------------------------------------------------
__global__ __launch_bounds__(512, 1)
void gemm_lse_mma(const float* __restrict__ log_tau, float* __restrict__ out) {
    extern __shared__ char smem[];
    __shared__ int s_last;
    uint32_t sA  = smem_u32(smem);
    uint32_t sB0 = sA + TILE_BYTES;
    uint32_t sB1 = sB0 + TILE_BYTES;

    int tid  = threadIdx.x;
    int lane = tid & 31;
    int warp = tid >> 5;
    int warp_m = warp >> 2;     // 0..3
    int warp_n = warp & 3;      // 0..3

    int slice   = blockIdx.x;
    int panel   = blockIdx.y;
    int row0    = panel * GBM;
    int colbase = slice * JSPAN;

    cp_tile(g_hzb + (size_t)row0 * MDIM,    sA,  tid);
    cp_tile(g_hyb + (size_t)colbase * MDIM, sB0, tid);
    CP_COMMIT();

    float Mconst = __expf(-log_tau[0]);
    const float L2E = 1.4426950408889634f;
    float ebias = -Mconst * L2E;

    uint32_t a_off = (uint32_t)((warp_m * 32 + (lane & 15)) * A_STRIDE_B + (lane >> 4) * 16);
    uint32_t b_off = (uint32_t)((warp_n * 32 + (lane & 7) + ((lane >> 4) << 3)) * A_STRIDE_B
                                + ((lane >> 3) & 1) * 16);

    float rowsum[4];
    #pragma unroll
    for (int i = 0; i < 4; i++) rowsum[i] = 0.f;

    float acc0[2][4][4], acc1[2][4][4];

    CP_WAIT0();
    __syncthreads();

    // software pipeline: tile n mma overlaps tile n-1 epilogue
    tile_step<false>(acc0, acc1, rowsum, 0, sA, sB0, sB1, a_off, b_off, colbase, tid, L2E, ebias);
    #pragma unroll 1
    for (int n = 1; n < TILES - 1; n += 2) {
        tile_step<true>(acc1, acc0, rowsum, n,     sA, sB0, sB1, a_off, b_off, colbase, tid, L2E, ebias);
        tile_step<true>(acc0, acc1, rowsum, n + 1, sA, sB0, sB1, a_off, b_off, colbase, tid, L2E, ebias);
    }
    tile_step<true>(acc1, acc0, rowsum, TILES - 1, sA, sB0, sB1, a_off, b_off, colbase, tid, L2E, ebias);
    // drain last tile's epilogue
    #pragma unroll
    for (int v = 0; v < 32; v++) {
        int mi = v >> 4, nj = (v >> 2) & 3, c = v & 3;
        rowsum[mi * 2 + (c >> 1)] += ex2f(fmaf(acc1[mi][nj][c], L2E, ebias));
    }

    // reduce: lanes sharing a row differ in bits 0-1
    #pragma unroll
    for (int i = 0; i < 4; i++) {
        rowsum[i] += __shfl_xor_sync(0xffffffffu, rowsum[i], 1);
        rowsum[i] += __shfl_xor_sync(0xffffffffu, rowsum[i], 2);
    }
    float* red = (float*)smem;   // reuse A area (compute done; synced above)
    if ((lane & 3) == 0) {
        int g = lane >> 2;
        #pragma unroll
        for (int i = 0; i < 4; i++) {
            int row = warp_m * 32 + (i >> 1) * 16 + g + (i & 1) * 8;
            red[row * 4 + warp_n] = rowsum[i];
        }
    }
    __syncthreads();
    if (tid < GBM) {
        float s = red[tid * 4] + red[tid * 4 + 1] + red[tid * 4 + 2] + red[tid * 4 + 3];
        g_psum[slice * BDIM + row0 + tid] = s;
    }
    __threadfence();
    __syncthreads();
    if (tid == 0)
        s_last = (atomicAdd(&g_done[panel], 1) == NSLICE - 1);
    __syncthreads();

    if (s_last) {
        __threadfence();
        if (tid < GBM) {
            int row = row0 + tid;
            float S = 0.f;
            #pragma unroll
            for (int sl = 0; sl < NSLICE; sl++) S += g_psum[sl * BDIM + row];
            float o = Mconst + logf(S) - g_diag[row] * Mconst - logf((float)BDIM);
            out[row] = fminf(fmaxf(o, -5.f), 15.f);
        }
    }
}

// ---------------------------------------------------------------------------
extern "C" void kernel_launch(void* const* d_in, const int* in_sizes, int n_in,
                              void* d_out, int out_size) {
    const float* z       = (const float*)d_in[0];
    const float* t       = (const float*)d_in[1];
    const float* e       = (const float*)d_in[2];
    const float* log_tau = (const float*)d_in[3];
    const float* E       = (const float*)d_in[4];
    const float* L       = (const float*)d_in[5];
    float* out = (float*)d_out;

    const int smem_sz = 3 * TILE_BYTES;   // 202,752 B
    cudaFuncSetAttribute(gemm_lse_mma, cudaFuncAttributeMaxDynamicSharedMemorySize, smem_sz);

    suffix_kernel<<<MDIM, MDIM>>>(E);
    prep_kernel<<<BDIM / 16, 512>>>(z, t, e, log_tau, E, L);
    gemm_lse_mma<<<dim3(NSLICE, NPANEL), 512, smem_sz>>>(log_tau, out);
}

// round 13
// speedup vs baseline: 1.5499x; 1.0011x over previous
#include <cuda_runtime.h>
#include <cuda_bf16.h>
#include <cstdint>
#include <math.h>

#define BDIM 8192
#define MDIM 256
#define NSLICE 2
#define JSPAN (BDIM / NSLICE)   // 4096
#define GBM 128
#define GBN 128
#define TILES (JSPAN / GBN)     // 32
#define NPANEL (BDIM / GBM)     // 64

#define A_STRIDE 264                     // bf16 elems per smem row (256 + 8 pad)
#define A_STRIDE_B (A_STRIDE * 2)        // 528 bytes
#define TILE_BYTES (GBM * A_STRIDE_B)    // 67584

// ---- device scratch (no allocations allowed) ----
__device__ __align__(16) __nv_bfloat16 g_hzb[BDIM * MDIM];  // bf16(hz * inv_tau2)
__device__ __align__(16) __nv_bfloat16 g_hyb[BDIM * MDIM];  // bf16(hy)
__device__ float g_Ssuf[MDIM * MDIM];
__device__ float g_diag[BDIM];
__device__ float g_psum[NSLICE * BDIM];
__device__ int   g_done[NPANEL];

// ============================ PTX helpers ============================
__device__ __forceinline__ uint32_t smem_u32(const void* p) {
    uint32_t a;
    asm("{ .reg .u64 t; cvta.to.shared.u64 t, %1; cvt.u32.u64 %0, t; }" : "=r"(a) : "l"(p));
    return a;
}
__device__ __forceinline__ void ldmatrix_x4(uint32_t* r, uint32_t addr) {
    asm volatile("ldmatrix.sync.aligned.m8n8.x4.shared.b16 {%0,%1,%2,%3}, [%4];"
                 : "=r"(r[0]), "=r"(r[1]), "=r"(r[2]), "=r"(r[3]) : "r"(addr));
}
__device__ __forceinline__ void mma_16816(float* c, const uint32_t* a,
                                          uint32_t b0, uint32_t b1) {
    asm volatile(
        "mma.sync.aligned.m16n8k16.row.col.f32.bf16.bf16.f32 "
        "{%0,%1,%2,%3}, {%4,%5,%6,%7}, {%8,%9}, {%0,%1,%2,%3};"
        : "+f"(c[0]), "+f"(c[1]), "+f"(c[2]), "+f"(c[3])
        : "r"(a[0]), "r"(a[1]), "r"(a[2]), "r"(a[3]), "r"(b0), "r"(b1));
}
__device__ __forceinline__ float ex2f(float x) {
    float y;
    asm("ex2.approx.ftz.f32 %0, %1;" : "=f"(y) : "f"(x));
    return y;
}
#define CP_ASYNC16(s, g) \
    asm volatile("cp.async.cg.shared.global [%0], [%1], 16;" :: "r"(s), "l"(g))
#define CP_COMMIT()  asm volatile("cp.async.commit_group;" ::: "memory")
#define CP_WAIT0()   asm volatile("cp.async.wait_group 0;" ::: "memory")

// copy 128 rows x 512B into padded smem (stride 528B), 256 threads
__device__ __forceinline__ void cp_tile(const __nv_bfloat16* __restrict__ g,
                                        uint32_t s, int tid) {
    int chunk = tid & 31;
    int row   = tid >> 5;          // 0..7
    const char* gp = (const char*)g + (size_t)row * 512 + chunk * 16;
    uint32_t sp = s + row * A_STRIDE_B + chunk * 16;
    #pragma unroll
    for (int r = 0; r < 16; r++) {
        CP_ASYNC16(sp, gp);
        gp += 8 * 512;
        sp += 8 * A_STRIDE_B;
    }
}

// ---------------------------------------------------------------------------
// Kernel 1: suffix sums of E rows via Hillis-Steele scan + zero counters
// ---------------------------------------------------------------------------
__global__ void suffix_kernel(const float* __restrict__ E) {
    __shared__ float buf[2][MDIM];
    int k = blockIdx.x, j = threadIdx.x;
    if (k == 0 && j < NPANEL) g_done[j] = 0;
    buf[0][j] = E[k * MDIM + j];
    int src = 0;
    #pragma unroll
    for (int off = 1; off < MDIM; off <<= 1) {
        __syncthreads();
        float v = buf[src][j] + ((j + off < MDIM) ? buf[src][j + off] : 0.f);
        buf[1 - src][j] = v;
        src ^= 1;
    }
    __syncthreads();
    g_Ssuf[j * MDIM + k] = buf[src][j];
}

// ---------------------------------------------------------------------------
// Kernel 2: prep — one warp per row (512-thread blocks, 16 warps)
// ---------------------------------------------------------------------------
__global__ __launch_bounds__(512)
void prep_kernel(const float* __restrict__ z,
                 const float* __restrict__ t,
                 const float* __restrict__ e,
                 const float* __restrict__ log_tau,
                 const float* __restrict__ E,
                 const float* __restrict__ L) {
    __shared__ float sL[MDIM];
    int tid = threadIdx.x;
    if (tid < MDIM) sL[tid] = L[tid];
    __syncthreads();

    int lane = tid & 31, warp = tid >> 5;
    int i = blockIdx.x * 16 + warp;

    float ti = t[i], ei = e[i];
    int lo = 0, hi = MDIM;
    while (lo < hi) { int mid = (lo + hi) >> 1; if (sL[mid] < ti) lo = mid + 1; else hi = mid; }
    int idx = lo;
    if (idx == 0) idx = 1;
    if (idx == MDIM) idx = MDIM - 1;

    float Llo = sL[idx - 1], Lhi = sL[idx];
    float slope_t = (ti - Llo) / (Lhi - Llo);
    float rden = 1.f / (float)(MDIM - idx);

    const float4* Elo4 = (const float4*)(E + (size_t)(idx - 1) * MDIM) + lane * 2;
    const float4* Ehi4 = (const float4*)(E + (size_t)idx * MDIM)       + lane * 2;
    const float4* Ss4  = (const float4*)(g_Ssuf + (size_t)idx * MDIM)  + lane * 2;
    const float4* z4   = (const float4*)(z + (size_t)i * MDIM)         + lane * 2;

    float yv[8], zv[8];
    float sy = 0.f, sz = 0.f, szy = 0.f;
    #pragma unroll
    for (int h = 0; h < 2; h++) {
        float4 el = Elo4[h], eh = Ehi4[h], ss = Ss4[h], zz = z4[h];
        float elc[4] = {el.x, el.y, el.z, el.w};
        float ehc[4] = {eh.x, eh.y, eh.z, eh.w};
        float ssc[4] = {ss.x, ss.y, ss.z, ss.w};
        float zzc[4] = {zz.x, zz.y, zz.z, zz.w};
        #pragma unroll
        for (int c = 0; c < 4; c++) {
            float ylin = elc[c] + (ehc[c] - elc[c]) * slope_t;
            float ycen = ssc[c] * rden;
            float y = ylin * ei + ycen * (1.f - ei);
            yv[h * 4 + c] = y;
            zv[h * 4 + c] = zzc[c];
            sy  = fmaf(y, y, sy);
            sz  = fmaf(zzc[c], zzc[c], sz);
            szy = fmaf(zzc[c], y, szy);
        }
    }
    #pragma unroll
    for (int o = 16; o; o >>= 1) {
        sy  += __shfl_xor_sync(0xffffffffu, sy,  o);
        sz  += __shfl_xor_sync(0xffffffffu, sz,  o);
        szy += __shfl_xor_sync(0xffffffffu, szy, o);
    }
    float ny = fmaxf(sqrtf(sy), 1e-12f);
    float nz = fmaxf(sqrtf(sz), 1e-12f);
    float inv_tau2 = __expf(-log_tau[0]);
    float scz = inv_tau2 / nz;
    float scy = 1.f / ny;

    uint4 hzp, hyp;
    __nv_bfloat162* hz2 = (__nv_bfloat162*)&hzp;
    __nv_bfloat162* hy2 = (__nv_bfloat162*)&hyp;
    #pragma unroll
    for (int p = 0; p < 4; p++) {
        hz2[p] = __floats2bfloat162_rn(zv[2*p] * scz, zv[2*p+1] * scz);
        hy2[p] = __floats2bfloat162_rn(yv[2*p] * scy, yv[2*p+1] * scy);
    }
    *(uint4*)(g_hzb + (size_t)i * MDIM + lane * 8) = hzp;
    *(uint4*)(g_hyb + (size_t)i * MDIM + lane * 8) = hyp;
    if (lane == 0) g_diag[i] = szy / (ny * nz);
}

// ---------------------------------------------------------------------------
// GEMM tile step (8 warps, 4M x 2N grid, warp tile 32x64):
// A k[0,128) comes from the persistent register cache aC; A k[128,256) and B
// stream from smem. Epilogue of accP (64 exps) interleaved 4 per ks.
// ---------------------------------------------------------------------------
template <bool EPI>
__device__ __forceinline__ void tile_step(
    float (&accC)[2][8][4], float (&accP)[2][8][4], float (&rowsum)[4],
    const uint32_t (&aC)[8][2][4],
    int n, uint32_t sA, uint32_t sB0, uint32_t sB1,
    uint32_t a_off, uint32_t b_off, int colbase, int tid,
    float L2E, float ebias)
{
    #pragma unroll
    for (int mi = 0; mi < 2; mi++)
        #pragma unroll
        for (int nj = 0; nj < 8; nj++)
            #pragma unroll
            for (int c = 0; c < 4; c++) accC[mi][nj][c] = 0.f;

    if (n + 1 < TILES) {
        cp_tile(g_hyb + (size_t)(colbase + (n + 1) * GBN) * MDIM,
                ((n + 1) & 1) ? sB1 : sB0, tid);
        CP_COMMIT();
    }
    uint32_t sBcur = (n & 1) ? sB1 : sB0;

    #pragma unroll
    for (int ks = 0; ks < 16; ks++) {
        uint32_t af[2][4];
        const uint32_t (*ap)[4];
        if (ks < 8) {
            ap = aC[ks];
        } else {
            #pragma unroll
            for (int mi = 0; mi < 2; mi++)
                ldmatrix_x4(af[mi], sA + a_off + mi * 16 * A_STRIDE_B + ks * 32);
            ap = af;
        }
        uint32_t bf[4][4];
        #pragma unroll
        for (int nb = 0; nb < 4; nb++)
            ldmatrix_x4(bf[nb], sBcur + b_off + nb * 16 * A_STRIDE_B + ks * 32);
        #pragma unroll
        for (int mi = 0; mi < 2; mi++)
            #pragma unroll
            for (int nj = 0; nj < 8; nj++)
                mma_16816(accC[mi][nj], ap[mi],
                          bf[nj >> 1][(nj & 1) * 2], bf[nj >> 1][(nj & 1) * 2 + 1]);
        if (EPI) {
            #pragma unroll
            for (int q = 0; q < 4; q++) {
                int v = ks * 4 + q;                        // 0..63
                int mi = v >> 5, nj = (v >> 2) & 7, c = v & 3;
                rowsum[mi * 2 + (c >> 1)] += ex2f(fmaf(accP[mi][nj][c], L2E, ebias));
            }
        }
    }
    CP_WAIT0();
    __syncthreads();
}

// ---------------------------------------------------------------------------
// Kernel 3: bf16 mma.sync GEMM, A-half register cached, merged finalize
// grid = (NSLICE, 64), block = 256 (8 warps: 4 M x 2 N, warp tile 32x64)
// ---------------------------------------------------------------------------
__global__ __launch_bounds__(256, 1)
void gemm_lse_mma(const float* __restrict__ log_tau, float* __restrict__ out) {
    extern __shared__ char smem[];
    __shared__ int s_last;
    uint32_t sA  = smem_u32(smem);
    uint32_t sB0 = sA + TILE_BYTES;
    uint32_t sB1 = sB0 + TILE_BYTES;

    int tid  = threadIdx.x;
    int lane = tid & 31;
    int warp = tid >> 5;
    int warp_m = warp >> 1;     // 0..3
    int warp_n = warp & 1;      // 0..1

    int slice   = blockIdx.x;
    int panel   = blockIdx.y;
    int row0    = panel * GBM;
    int colbase = slice * JSPAN;

    cp_tile(g_hzb + (size_t)row0 * MDIM,    sA,  tid);
    cp_tile(g_hyb + (size_t)colbase * MDIM, sB0, tid);
    CP_COMMIT();

    float Mconst = __expf(-log_tau[0]);
    const float L2E = 1.4426950408889634f;
    float ebias = -Mconst * L2E;

    uint32_t a_off = (uint32_t)((warp_m * 32 + (lane & 15)) * A_STRIDE_B + (lane >> 4) * 16);
    uint32_t b_off = (uint32_t)((warp_n * 64 + (lane & 7) + ((lane >> 4) << 3)) * A_STRIDE_B
                                + ((lane >> 3) & 1) * 16);

    float rowsum[4];
    #pragma unroll
    for (int i = 0; i < 4; i++) rowsum[i] = 0.f;

    float acc0[2][8][4], acc1[2][8][4];

    CP_WAIT0();
    __syncthreads();

    // Register-cache A fragments for k in [0, 128): loaded once per panel.
    uint32_t aC[8][2][4];
    #pragma unroll
    for (int ks = 0; ks < 8; ks++)
        #pragma unroll
        for (int mi = 0; mi < 2; mi++)
            ldmatrix_x4(aC[ks][mi], sA + a_off + mi * 16 * A_STRIDE_B + ks * 32);

    // software pipeline: tile n mma overlaps tile n-1 epilogue
    tile_step<false>(acc0, acc1, rowsum, aC, 0, sA, sB0, sB1, a_off, b_off, colbase, tid, L2E, ebias);
    #pragma unroll 1
    for (int n = 1; n < TILES - 1; n += 2) {
        tile_step<true>(acc1, acc0, rowsum, aC, n,     sA, sB0, sB1, a_off, b_off, colbase, tid, L2E, ebias);
        tile_step<true>(acc0, acc1, rowsum, aC, n + 1, sA, sB0, sB1, a_off, b_off, colbase, tid, L2E, ebias);
    }
    tile_step<true>(acc1, acc0, rowsum, aC, TILES - 1, sA, sB0, sB1, a_off, b_off, colbase, tid, L2E, ebias);
    // drain last tile's epilogue
    #pragma unroll
    for (int v = 0; v < 64; v++) {
        int mi = v >> 5, nj = (v >> 2) & 7, c = v & 3;
        rowsum[mi * 2 + (c >> 1)] += ex2f(fmaf(acc1[mi][nj][c], L2E, ebias));
    }

    // reduce: lanes sharing a row differ in bits 0-1
    #pragma unroll
    for (int i = 0; i < 4; i++) {
        rowsum[i] += __shfl_xor_sync(0xffffffffu, rowsum[i], 1);
        rowsum[i] += __shfl_xor_sync(0xffffffffu, rowsum[i], 2);
    }
    float* red = (float*)smem;   // reuse A area (all A reads done; synced above)
    if ((lane & 3) == 0) {
        int g = lane >> 2;
        #pragma unroll
        for (int i = 0; i < 4; i++) {
            int row = warp_m * 32 + (i >> 1) * 16 + g + (i & 1) * 8;
            red[row * 2 + warp_n] = rowsum[i];
        }
    }
    __syncthreads();
    if (tid < GBM) {
        float s = red[tid * 2] + red[tid * 2 + 1];
        g_psum[slice * BDIM + row0 + tid] = s;
    }
    __threadfence();
    __syncthreads();
    if (tid == 0)
        s_last = (atomicAdd(&g_done[panel], 1) == NSLICE - 1);
    __syncthreads();

    if (s_last) {
        __threadfence();
        if (tid < GBM) {
            int row = row0 + tid;
            float S = 0.f;
            #pragma unroll
            for (int sl = 0; sl < NSLICE; sl++) S += g_psum[sl * BDIM + row];
            float o = Mconst + logf(S) - g_diag[row] * Mconst - logf((float)BDIM);
            out[row] = fminf(fmaxf(o, -5.f), 15.f);
        }
    }
}

// ---------------------------------------------------------------------------
extern "C" void kernel_launch(void* const* d_in, const int* in_sizes, int n_in,
                              void* d_out, int out_size) {
    const float* z       = (const float*)d_in[0];
    const float* t       = (const float*)d_in[1];
    const float* e       = (const float*)d_in[2];
    const float* log_tau = (const float*)d_in[3];
    const float* E       = (const float*)d_in[4];
    const float* L       = (const float*)d_in[5];
    float* out = (float*)d_out;

    const int smem_sz = 3 * TILE_BYTES;   // 202,752 B
    cudaFuncSetAttribute(gemm_lse_mma, cudaFuncAttributeMaxDynamicSharedMemorySize, smem_sz);

    suffix_kernel<<<MDIM, MDIM>>>(E);
    prep_kernel<<<BDIM / 16, 512>>>(z, t, e, log_tau, E, L);
    gemm_lse_mma<<<dim3(NSLICE, NPANEL), 256, smem_sz>>>(log_tau, out);
}